// round 4
// baseline (speedup 1.0000x reference)
#include <cuda_runtime.h>
#include <cstdint>

#define FEAT 128
#define HID  64
#define NMAX 100000
#define EMAX 1600000

// Scratch (device globals — no runtime allocation allowed)
__device__ float g_h1[NMAX * HID];        // x@W1+b1
__device__ float g_a1[NMAX * HID];        // spmm1 output (only needed rows valid)
__device__ float g_h3[NMAX * HID];        // (relu(a1)*mask)@W2+b2
__device__ int   g_counts[NMAX];          // row degree
__device__ int   g_rowptr[NMAX + 1];      // CSR row pointers
__device__ int   g_cursor[NMAX];          // scatter cursors
__device__ int2  g_csr[EMAX];             // {col, val bits} sorted by row
__device__ int   g_blocksums[256];
__device__ unsigned char g_need[NMAX];    // node needed as spmm1 output row?

// ---------------------------------------------------------------------------
__global__ void k_zero(int n) {
    int tid = blockIdx.x * blockDim.x + threadIdx.x;
    int stride = gridDim.x * blockDim.x;
    for (int t = tid; t < n; t += stride) {
        g_counts[t] = 0;
        g_need[t] = 0;
    }
}

__global__ void k_count(const int* __restrict__ row, int E) {
    int e = blockIdx.x * blockDim.x + threadIdx.x;
    if (e < E) atomicAdd(&g_counts[__ldg(row + e)], 1);
}

// ---------------------------------------------------------------------------
// Scan stage 1: per-block (1024 elems) exclusive partials + block sums
// ---------------------------------------------------------------------------
__global__ void __launch_bounds__(256) k_scan1(int n) {
    __shared__ int ssum[256];
    int t = threadIdx.x;
    int base = blockIdx.x * 1024 + t * 4;
    int v[4], s = 0;
#pragma unroll
    for (int j = 0; j < 4; j++) {
        int i = base + j;
        v[j] = (i < n) ? g_counts[i] : 0;
        s += v[j];
    }
    ssum[t] = s;
    __syncthreads();
#pragma unroll
    for (int d = 1; d < 256; d <<= 1) {
        int add = (t >= d) ? ssum[t - d] : 0;
        __syncthreads();
        ssum[t] += add;
        __syncthreads();
    }
    int run = ssum[t] - s;
#pragma unroll
    for (int j = 0; j < 4; j++) {
        int i = base + j;
        if (i < n) g_rowptr[i] = run;
        run += v[j];
    }
    if (t == 255) g_blocksums[blockIdx.x] = ssum[255];
}

// ---------------------------------------------------------------------------
// Scan stage 2+3 fused: every block redundantly scans the <=256 block sums in
// smem, then adds its offset. Also inits cursors + caps rowptr.
// ---------------------------------------------------------------------------
__global__ void __launch_bounds__(256) k_scan3(int n, int E, int nb) {
    __shared__ int s[256];
    int t = threadIdx.x;
    int bsv = (t < nb) ? g_blocksums[t] : 0;
    s[t] = bsv;
    __syncthreads();
#pragma unroll
    for (int d = 1; d < 256; d <<= 1) {
        int add = (t >= d) ? s[t - d] : 0;
        __syncthreads();
        s[t] += add;
        __syncthreads();
    }
    // s[] is now inclusive scan; exclusive offset for block j is s[j-1]
    int i = blockIdx.x * blockDim.x + t;
    if (i < n) {
        int j = i >> 10;
        int off = (j > 0) ? s[j - 1] : 0;
        int v = g_rowptr[i] + off;
        g_rowptr[i] = v;
        g_cursor[i] = v;
    }
    if (i == 0) g_rowptr[n] = E;
}

// ---------------------------------------------------------------------------
__global__ void k_scatter(const float* __restrict__ vals,
                          const int* __restrict__ row,
                          const int* __restrict__ col, int E) {
    int e = blockIdx.x * blockDim.x + threadIdx.x;
    if (e >= E) return;
    int r = __ldg(row + e);
    int pos = atomicAdd(&g_cursor[r], 1);
    g_csr[pos] = make_int2(__ldg(col + e), __float_as_int(__ldg(vals + e)));
}

__global__ void k_mark_need(const int* __restrict__ idx, int nidx) {
    int g = blockIdx.x * blockDim.x + threadIdx.x;
    int i = g >> 4;
    if (i >= nidx) return;
    int lane = g & 15;
    int r = __ldg(idx + i);
    int s = g_rowptr[r], eEnd = g_rowptr[r + 1];
    for (int e = s + lane; e < eEnd; e += 16)
        g_need[g_csr[e].x] = 1;
}

// ---------------------------------------------------------------------------
// GEMM with packed fma.rn.f32x2 and DUPLICATED A-tile in smem:
// As2[r][kk] = {a, a}  ->  LDS.64 directly yields the packed FFMA2 operand.
// Block: 64 rows x 64 cols, 256 threads, thread tile 2 rows x 8 cols.
// KCH=16 to fit static smem (Ws 32KB + As2 9KB).
// ---------------------------------------------------------------------------
#define KCH 16
#define A2STRIDE 18   // float2 units; 18*8=144B rows (16B aligned, conflict-free)

__device__ __forceinline__ void fma2(unsigned long long& acc,
                                     unsigned long long a,
                                     unsigned long long b) {
    asm("fma.rn.f32x2 %0, %1, %2, %0;" : "+l"(acc) : "l"(a), "l"(b));
}

template <int K, bool SECOND>
__global__ void __launch_bounds__(256) k_gemm(const float* __restrict__ Aext,
                                              const float* __restrict__ W,
                                              const float* __restrict__ bias,
                                              const float* __restrict__ mask,
                                              int nrows) {
    __shared__ float Ws[K * HID];              // K=128 -> 32 KB
    __shared__ float2 As2[64 * A2STRIDE];      // 9 KB

    const float* A = SECOND ? g_a1 : Aext;
    float* out = SECOND ? g_h3 : g_h1;

    int tid = threadIdx.x;
    int tx = tid & 7;
    int ty = tid >> 3;
    int row0 = blockIdx.x * 64;

    for (int t = tid; t < K * HID / 4; t += 256)
        reinterpret_cast<float4*>(Ws)[t] =
            reinterpret_cast<const float4*>(W)[t];

    union F2 { unsigned long long u; float2 f; };
    F2 acc[2][4];
#pragma unroll
    for (int i = 0; i < 2; i++)
#pragma unroll
        for (int p = 0; p < 4; p++) acc[i][p].u = 0ull;

    const int vpr = K / 4;

    for (int kc = 0; kc < K; kc += KCH) {
        __syncthreads();
        // Stage A chunk duplicated: 64 rows x 16 k; one float4 per thread.
        {
            int r = tid >> 2;          // 0..63
            int kv = tid & 3;          // 0..3
            float4 a = make_float4(0.f, 0.f, 0.f, 0.f);
            int gr = row0 + r;
            if (gr < nrows) {
                a = reinterpret_cast<const float4*>(A)[(size_t)gr * vpr + (kc / 4) + kv];
                if (SECOND) {
                    float4 m = reinterpret_cast<const float4*>(mask)[(size_t)gr * vpr + (kc / 4) + kv];
                    a.x = fmaxf(a.x, 0.f) * m.x;
                    a.y = fmaxf(a.y, 0.f) * m.y;
                    a.z = fmaxf(a.z, 0.f) * m.z;
                    a.w = fmaxf(a.w, 0.f) * m.w;
                }
            }
            float4* p = reinterpret_cast<float4*>(&As2[r * A2STRIDE + kv * 4]);
            p[0] = make_float4(a.x, a.x, a.y, a.y);
            p[1] = make_float4(a.z, a.z, a.w, a.w);
        }
        __syncthreads();

#pragma unroll
        for (int kk = 0; kk < KCH; kk++) {
            int k = kc + kk;
            ulonglong2 wlo = *reinterpret_cast<const ulonglong2*>(&Ws[k * HID + 4 * tx]);
            ulonglong2 whi = *reinterpret_cast<const ulonglong2*>(&Ws[k * HID + 4 * tx + 32]);
#pragma unroll
            for (int i = 0; i < 2; i++) {
                unsigned long long aa =
                    *reinterpret_cast<const unsigned long long*>(&As2[(ty * 2 + i) * A2STRIDE + kk]);
                fma2(acc[i][0].u, aa, wlo.x);
                fma2(acc[i][1].u, aa, wlo.y);
                fma2(acc[i][2].u, aa, whi.x);
                fma2(acc[i][3].u, aa, whi.y);
            }
        }
    }

    float4 blo = *reinterpret_cast<const float4*>(bias + 4 * tx);
    float4 bhi = *reinterpret_cast<const float4*>(bias + 4 * tx + 32);
#pragma unroll
    for (int i = 0; i < 2; i++) {
        int r = row0 + ty * 2 + i;
        if (r >= nrows) continue;
        float4 olo, ohi;
        olo.x = acc[i][0].f.x + blo.x;  olo.y = acc[i][0].f.y + blo.y;
        olo.z = acc[i][1].f.x + blo.z;  olo.w = acc[i][1].f.y + blo.w;
        ohi.x = acc[i][2].f.x + bhi.x;  ohi.y = acc[i][2].f.y + bhi.y;
        ohi.z = acc[i][3].f.x + bhi.z;  ohi.w = acc[i][3].f.y + bhi.w;
        *reinterpret_cast<float4*>(&out[(size_t)r * HID + 4 * tx]) = olo;
        *reinterpret_cast<float4*>(&out[(size_t)r * HID + 4 * tx + 32]) = ohi;
    }
}

// ---------------------------------------------------------------------------
// CSR SpMM row body: 16 lanes per row, register accumulation, unroll-4 (MLP=4)
// ---------------------------------------------------------------------------
__device__ __forceinline__ float4 csr_row_accum(const float* __restrict__ src,
                                                int s, int eEnd, int lane) {
    float4 acc = make_float4(0.f, 0.f, 0.f, 0.f);
    int e = s;
    for (; e + 3 < eEnd; e += 4) {
        int2 cv0 = __ldg(&g_csr[e]);
        int2 cv1 = __ldg(&g_csr[e + 1]);
        int2 cv2 = __ldg(&g_csr[e + 2]);
        int2 cv3 = __ldg(&g_csr[e + 3]);
        float4 x0 = __ldg(reinterpret_cast<const float4*>(src + (size_t)cv0.x * HID) + lane);
        float4 x1 = __ldg(reinterpret_cast<const float4*>(src + (size_t)cv1.x * HID) + lane);
        float4 x2 = __ldg(reinterpret_cast<const float4*>(src + (size_t)cv2.x * HID) + lane);
        float4 x3 = __ldg(reinterpret_cast<const float4*>(src + (size_t)cv3.x * HID) + lane);
        float v0 = __int_as_float(cv0.y), v1 = __int_as_float(cv1.y);
        float v2 = __int_as_float(cv2.y), v3 = __int_as_float(cv3.y);
        acc.x += v0 * x0.x + v1 * x1.x + v2 * x2.x + v3 * x3.x;
        acc.y += v0 * x0.y + v1 * x1.y + v2 * x2.y + v3 * x3.y;
        acc.z += v0 * x0.z + v1 * x1.z + v2 * x2.z + v3 * x3.z;
        acc.w += v0 * x0.w + v1 * x1.w + v2 * x2.w + v3 * x3.w;
    }
    for (; e < eEnd; e++) {
        int2 cv = __ldg(&g_csr[e]);
        float4 x = __ldg(reinterpret_cast<const float4*>(src + (size_t)cv.x * HID) + lane);
        float v = __int_as_float(cv.y);
        acc.x += v * x.x;  acc.y += v * x.y;
        acc.z += v * x.z;  acc.w += v * x.w;
    }
    return acc;
}

__global__ void __launch_bounds__(256) k_spmm1(int n) {
    int g = blockIdx.x * blockDim.x + threadIdx.x;
    int r = g >> 4;
    if (r >= n) return;
    if (!g_need[r]) return;
    int lane = g & 15;
    int s = g_rowptr[r], eEnd = g_rowptr[r + 1];
    float4 acc = csr_row_accum(g_h1, s, eEnd, lane);
    reinterpret_cast<float4*>(g_a1 + (size_t)r * HID)[lane] = acc;
}

__global__ void __launch_bounds__(256) k_spmm2(const int* __restrict__ idx,
                                               float* __restrict__ out,
                                               int nidx) {
    int g = blockIdx.x * blockDim.x + threadIdx.x;
    int i = g >> 4;
    if (i >= nidx) return;
    int lane = g & 15;
    int r = __ldg(idx + i);
    int s = g_rowptr[r], eEnd = g_rowptr[r + 1];
    float4 acc = csr_row_accum(g_h3, s, eEnd, lane);
    reinterpret_cast<float4*>(out + (size_t)i * HID)[lane] = acc;
}

// ---------------------------------------------------------------------------
extern "C" void kernel_launch(void* const* d_in, const int* in_sizes, int n_in,
                              void* d_out, int out_size) {
    const float* x    = (const float*)d_in[0];
    const float* vals = (const float*)d_in[1];
    const float* W1   = (const float*)d_in[2];
    const float* b1   = (const float*)d_in[3];
    const float* W2   = (const float*)d_in[4];
    const float* b2   = (const float*)d_in[5];
    const float* mask = (const float*)d_in[6];
    const int*   row  = (const int*)d_in[7];
    const int*   col  = (const int*)d_in[8];
    const int*   idx  = (const int*)d_in[9];

    int n    = in_sizes[0] / FEAT;   // 100000
    int E    = in_sizes[1];          // 1600000
    int nidx = in_sizes[9];          // 10000

    float* out = (float*)d_out;
    int nb = (n + 1023) / 1024;      // 98 scan blocks

    // One-time side-stream + events (host resources, not device memory).
    static cudaStream_t s2 = nullptr;
    static cudaEvent_t evFork = nullptr, evJoin = nullptr;
    if (s2 == nullptr) {
        cudaStreamCreateWithFlags(&s2, cudaStreamNonBlocking);
        cudaEventCreateWithFlags(&evFork, cudaEventDisableTiming);
        cudaEventCreateWithFlags(&evJoin, cudaEventDisableTiming);
    }

    // Fork: CSR build on s2 runs concurrently with GEMM1 on the main stream.
    cudaEventRecord(evFork, 0);
    cudaStreamWaitEvent(s2, evFork, 0);

    k_zero<<<256, 256, 0, s2>>>(n);
    k_count<<<(E + 255) / 256, 256, 0, s2>>>(row, E);
    k_scan1<<<nb, 256, 0, s2>>>(n);
    k_scan3<<<(n + 255) / 256, 256, 0, s2>>>(n, E, nb);
    k_scatter<<<(E + 255) / 256, 256, 0, s2>>>(vals, row, col, E);
    k_mark_need<<<(nidx * 16 + 255) / 256, 256, 0, s2>>>(idx, nidx);

    k_gemm<FEAT, false><<<(n + 63) / 64, 256>>>(x, W1, b1, nullptr, n);

    // Join: spmm1 needs both h1 (main) and CSR+need (s2).
    cudaEventRecord(evJoin, s2);
    cudaStreamWaitEvent(0, evJoin, 0);

    k_spmm1<<<(n * 16 + 255) / 256, 256>>>(n);
    k_gemm<HID, true><<<(n + 63) / 64, 256>>>(nullptr, W2, b2, mask, n);
    k_spmm2<<<(nidx * 16 + 255) / 256, 256>>>(idx, out, nidx);
}

// round 5
// speedup vs baseline: 1.0696x; 1.0696x over previous
#include <cuda_runtime.h>
#include <cstdint>

#define FEAT 128
#define HID  64
#define NMAX 100000
#define EMAX 1600000

// Scratch (device globals — no runtime allocation allowed)
__device__ float g_h1[NMAX * HID];        // x@W1+b1
__device__ float g_a1[NMAX * HID];        // spmm1 output (only needed rows valid)
__device__ float g_h3[NMAX * HID];        // (relu(a1)*mask)@W2+b2
__device__ int   g_counts[NMAX];          // row degree
__device__ int   g_rowptr[NMAX + 1];      // CSR row pointers
__device__ int   g_cursor[NMAX];          // scatter cursors
__device__ int2  g_csr[EMAX];             // {col, val bits} sorted by row
__device__ int   g_blocksums[256];
__device__ unsigned char g_need[NMAX];    // node needed as spmm1 output row?
__device__ unsigned char g_keep[NMAX];    // node in idx set?

// ---------------------------------------------------------------------------
// Init: zero counts + need + keep
// ---------------------------------------------------------------------------
__global__ void k_init(int n) {
    int tid = blockIdx.x * blockDim.x + threadIdx.x;
    int stride = gridDim.x * blockDim.x;
    for (int t = tid; t < n; t += stride) {
        g_counts[t] = 0;
        g_need[t] = 0;
        g_keep[t] = 0;
    }
}

__global__ void k_keep(const int* __restrict__ idx, int nidx) {
    int i = blockIdx.x * blockDim.x + threadIdx.x;
    if (i < nidx) g_keep[__ldg(idx + i)] = 1;
}

// Mark needed a1 rows straight from the raw edge list (independent of CSR):
// out rows = idx set; a1[c] needed iff exists edge (r in idxset) -> c.
__global__ void k_need(const int* __restrict__ row,
                       const int* __restrict__ col, int E) {
    int e = blockIdx.x * blockDim.x + threadIdx.x;
    if (e >= E) return;
    if (g_keep[__ldg(row + e)]) g_need[__ldg(col + e)] = 1;
}

__global__ void k_count(const int* __restrict__ row, int E) {
    int e = blockIdx.x * blockDim.x + threadIdx.x;
    if (e < E) atomicAdd(&g_counts[__ldg(row + e)], 1);
}

// ---------------------------------------------------------------------------
// Scan stage 1: per-block (1024 elems) exclusive partials + block sums
// ---------------------------------------------------------------------------
__global__ void __launch_bounds__(256) k_scan1(int n) {
    __shared__ int ssum[256];
    int t = threadIdx.x;
    int base = blockIdx.x * 1024 + t * 4;
    int v[4], s = 0;
#pragma unroll
    for (int j = 0; j < 4; j++) {
        int i = base + j;
        v[j] = (i < n) ? g_counts[i] : 0;
        s += v[j];
    }
    ssum[t] = s;
    __syncthreads();
#pragma unroll
    for (int d = 1; d < 256; d <<= 1) {
        int add = (t >= d) ? ssum[t - d] : 0;
        __syncthreads();
        ssum[t] += add;
        __syncthreads();
    }
    int run = ssum[t] - s;
#pragma unroll
    for (int j = 0; j < 4; j++) {
        int i = base + j;
        if (i < n) g_rowptr[i] = run;
        run += v[j];
    }
    if (t == 255) g_blocksums[blockIdx.x] = ssum[255];
}

// ---------------------------------------------------------------------------
// Scan stage 2+3 fused: every block redundantly scans the <=256 block sums
// in smem, adds its offset, inits cursors, caps rowptr.
// ---------------------------------------------------------------------------
__global__ void __launch_bounds__(256) k_scan3(int n, int E, int nb) {
    __shared__ int s[256];
    int t = threadIdx.x;
    int bsv = (t < nb) ? g_blocksums[t] : 0;
    s[t] = bsv;
    __syncthreads();
#pragma unroll
    for (int d = 1; d < 256; d <<= 1) {
        int add = (t >= d) ? s[t - d] : 0;
        __syncthreads();
        s[t] += add;
        __syncthreads();
    }
    int i = blockIdx.x * blockDim.x + t;
    if (i < n) {
        int j = i >> 10;
        int off = (j > 0) ? s[j - 1] : 0;
        int v = g_rowptr[i] + off;
        g_rowptr[i] = v;
        g_cursor[i] = v;
    }
    if (i == 0) g_rowptr[n] = E;
}

// ---------------------------------------------------------------------------
__global__ void k_scatter(const float* __restrict__ vals,
                          const int* __restrict__ row,
                          const int* __restrict__ col, int E) {
    int e = blockIdx.x * blockDim.x + threadIdx.x;
    if (e >= E) return;
    int r = __ldg(row + e);
    int pos = atomicAdd(&g_cursor[r], 1);
    g_csr[pos] = make_int2(__ldg(col + e), __float_as_int(__ldg(vals + e)));
}

// ---------------------------------------------------------------------------
// GEMM with packed fma.rn.f32x2 (R3-proven version).
// Block tile: 64 rows x 64 cols, 256 threads; thread tile 2 rows x 8 cols.
// K chunked by 32 into padded smem (stride 34 -> conflict-free A broadcast).
// ---------------------------------------------------------------------------
#define KCH 32
#define ASTRIDE (KCH + 2)

__device__ __forceinline__ void fma2(unsigned long long& acc,
                                     unsigned long long a,
                                     unsigned long long b) {
    asm("fma.rn.f32x2 %0, %1, %2, %0;" : "+l"(acc) : "l"(a), "l"(b));
}

template <int K, bool SECOND>
__global__ void __launch_bounds__(256) k_gemm(const float* __restrict__ Aext,
                                              const float* __restrict__ W,
                                              const float* __restrict__ bias,
                                              const float* __restrict__ mask,
                                              int nrows) {
    __shared__ float Ws[K * HID];
    __shared__ float As[64 * ASTRIDE];

    const float* A = SECOND ? g_a1 : Aext;
    float* out = SECOND ? g_h3 : g_h1;

    int tid = threadIdx.x;
    int tx = tid & 7;
    int ty = tid >> 3;
    int row0 = blockIdx.x * 64;

    for (int t = tid; t < K * HID / 4; t += 256)
        reinterpret_cast<float4*>(Ws)[t] =
            reinterpret_cast<const float4*>(W)[t];

    union F2 { unsigned long long u; float2 f; };
    F2 acc[2][4];
#pragma unroll
    for (int i = 0; i < 2; i++)
#pragma unroll
        for (int p = 0; p < 4; p++) acc[i][p].u = 0ull;

    const int vpr = K / 4;

    for (int kc = 0; kc < K; kc += KCH) {
        __syncthreads();
        for (int t = tid; t < 64 * (KCH / 4); t += 256) {
            int r = t >> 3;
            int kv = t & 7;
            float4 a = make_float4(0.f, 0.f, 0.f, 0.f);
            int gr = row0 + r;
            if (gr < nrows) {
                a = reinterpret_cast<const float4*>(A)[(size_t)gr * vpr + (kc / 4) + kv];
                if (SECOND) {
                    float4 m = reinterpret_cast<const float4*>(mask)[(size_t)gr * vpr + (kc / 4) + kv];
                    a.x = fmaxf(a.x, 0.f) * m.x;
                    a.y = fmaxf(a.y, 0.f) * m.y;
                    a.z = fmaxf(a.z, 0.f) * m.z;
                    a.w = fmaxf(a.w, 0.f) * m.w;
                }
            }
            float2* p = reinterpret_cast<float2*>(&As[r * ASTRIDE + kv * 4]);
            p[0] = make_float2(a.x, a.y);
            p[1] = make_float2(a.z, a.w);
        }
        __syncthreads();

#pragma unroll 8
        for (int kk = 0; kk < KCH; kk++) {
            int k = kc + kk;
            ulonglong2 wlo = *reinterpret_cast<const ulonglong2*>(&Ws[k * HID + 4 * tx]);
            ulonglong2 whi = *reinterpret_cast<const ulonglong2*>(&Ws[k * HID + 4 * tx + 32]);
#pragma unroll
            for (int i = 0; i < 2; i++) {
                float a = As[(ty * 2 + i) * ASTRIDE + kk];
                unsigned long long aa;
                asm("mov.b64 %0, {%1, %1};" : "=l"(aa) : "f"(a));
                fma2(acc[i][0].u, aa, wlo.x);
                fma2(acc[i][1].u, aa, wlo.y);
                fma2(acc[i][2].u, aa, whi.x);
                fma2(acc[i][3].u, aa, whi.y);
            }
        }
    }

    float4 blo = *reinterpret_cast<const float4*>(bias + 4 * tx);
    float4 bhi = *reinterpret_cast<const float4*>(bias + 4 * tx + 32);
#pragma unroll
    for (int i = 0; i < 2; i++) {
        int r = row0 + ty * 2 + i;
        if (r >= nrows) continue;
        float4 olo, ohi;
        olo.x = acc[i][0].f.x + blo.x;  olo.y = acc[i][0].f.y + blo.y;
        olo.z = acc[i][1].f.x + blo.z;  olo.w = acc[i][1].f.y + blo.w;
        ohi.x = acc[i][2].f.x + bhi.x;  ohi.y = acc[i][2].f.y + bhi.y;
        ohi.z = acc[i][3].f.x + bhi.z;  ohi.w = acc[i][3].f.y + bhi.w;
        *reinterpret_cast<float4*>(&out[(size_t)r * HID + 4 * tx]) = olo;
        *reinterpret_cast<float4*>(&out[(size_t)r * HID + 4 * tx + 32]) = ohi;
    }
}

// ---------------------------------------------------------------------------
// CSR SpMM row body: 16 lanes per row, register accumulation, unroll-2
// (R3-proven).
// ---------------------------------------------------------------------------
__device__ __forceinline__ float4 csr_row_accum(const float* __restrict__ src,
                                                int s, int eEnd, int lane) {
    float4 acc = make_float4(0.f, 0.f, 0.f, 0.f);
    int e = s;
    for (; e + 1 < eEnd; e += 2) {
        int2 cv0 = __ldg(&g_csr[e]);
        int2 cv1 = __ldg(&g_csr[e + 1]);
        float4 x0 = __ldg(reinterpret_cast<const float4*>(src + (size_t)cv0.x * HID) + lane);
        float4 x1 = __ldg(reinterpret_cast<const float4*>(src + (size_t)cv1.x * HID) + lane);
        float v0 = __int_as_float(cv0.y);
        float v1 = __int_as_float(cv1.y);
        acc.x += v0 * x0.x + v1 * x1.x;
        acc.y += v0 * x0.y + v1 * x1.y;
        acc.z += v0 * x0.z + v1 * x1.z;
        acc.w += v0 * x0.w + v1 * x1.w;
    }
    if (e < eEnd) {
        int2 cv = __ldg(&g_csr[e]);
        float4 x = __ldg(reinterpret_cast<const float4*>(src + (size_t)cv.x * HID) + lane);
        float v = __int_as_float(cv.y);
        acc.x += v * x.x;  acc.y += v * x.y;
        acc.z += v * x.z;  acc.w += v * x.w;
    }
    return acc;
}

__global__ void __launch_bounds__(256) k_spmm1(int n) {
    int g = blockIdx.x * blockDim.x + threadIdx.x;
    int r = g >> 4;
    if (r >= n) return;
    if (!g_need[r]) return;
    int lane = g & 15;
    int s = g_rowptr[r], eEnd = g_rowptr[r + 1];
    float4 acc = csr_row_accum(g_h1, s, eEnd, lane);
    reinterpret_cast<float4*>(g_a1 + (size_t)r * HID)[lane] = acc;
}

__global__ void __launch_bounds__(256) k_spmm2(const int* __restrict__ idx,
                                               float* __restrict__ out,
                                               int nidx) {
    int g = blockIdx.x * blockDim.x + threadIdx.x;
    int i = g >> 4;
    if (i >= nidx) return;
    int lane = g & 15;
    int r = __ldg(idx + i);
    int s = g_rowptr[r], eEnd = g_rowptr[r + 1];
    float4 acc = csr_row_accum(g_h3, s, eEnd, lane);
    reinterpret_cast<float4*>(out + (size_t)i * HID)[lane] = acc;
}

// ---------------------------------------------------------------------------
extern "C" void kernel_launch(void* const* d_in, const int* in_sizes, int n_in,
                              void* d_out, int out_size) {
    const float* x    = (const float*)d_in[0];
    const float* vals = (const float*)d_in[1];
    const float* W1   = (const float*)d_in[2];
    const float* b1   = (const float*)d_in[3];
    const float* W2   = (const float*)d_in[4];
    const float* b2   = (const float*)d_in[5];
    const float* mask = (const float*)d_in[6];
    const int*   row  = (const int*)d_in[7];
    const int*   col  = (const int*)d_in[8];
    const int*   idx  = (const int*)d_in[9];

    int n    = in_sizes[0] / FEAT;   // 100000
    int E    = in_sizes[1];          // 1600000
    int nidx = in_sizes[9];          // 10000

    float* out = (float*)d_out;
    int nb = (n + 1023) / 1024;      // 98 scan blocks

    // One-time side-streams + events (host resources, not device memory).
    static cudaStream_t s2 = nullptr, s3 = nullptr;
    static cudaEvent_t evFork = nullptr, evInit = nullptr;
    static cudaEvent_t evJoin2 = nullptr, evJoin3 = nullptr;
    if (s2 == nullptr) {
        cudaStreamCreateWithFlags(&s2, cudaStreamNonBlocking);
        cudaStreamCreateWithFlags(&s3, cudaStreamNonBlocking);
        cudaEventCreateWithFlags(&evFork, cudaEventDisableTiming);
        cudaEventCreateWithFlags(&evInit, cudaEventDisableTiming);
        cudaEventCreateWithFlags(&evJoin2, cudaEventDisableTiming);
        cudaEventCreateWithFlags(&evJoin3, cudaEventDisableTiming);
    }

    // Fork: side-chains run concurrently with GEMM1 on the main stream.
    cudaEventRecord(evFork, 0);
    cudaStreamWaitEvent(s2, evFork, 0);

    // s2: init, then CSR chain
    k_init<<<256, 256, 0, s2>>>(n);
    cudaEventRecord(evInit, s2);
    k_count<<<(E + 255) / 256, 256, 0, s2>>>(row, E);
    k_scan1<<<nb, 256, 0, s2>>>(n);
    k_scan3<<<(n + 255) / 256, 256, 0, s2>>>(n, E, nb);
    k_scatter<<<(E + 255) / 256, 256, 0, s2>>>(vals, row, col, E);
    cudaEventRecord(evJoin2, s2);

    // s3: keep + need marking (only depends on init)
    cudaStreamWaitEvent(s3, evInit, 0);
    k_keep<<<(nidx + 255) / 256, 256, 0, s3>>>(idx, nidx);
    k_need<<<(E + 255) / 256, 256, 0, s3>>>(row, col, E);
    cudaEventRecord(evJoin3, s3);

    // main: GEMM1 concurrent with both side-chains
    k_gemm<FEAT, false><<<(n + 63) / 64, 256>>>(x, W1, b1, nullptr, n);

    // Join: spmm1 needs h1 (main), CSR (s2), need flags (s3).
    cudaStreamWaitEvent(0, evJoin2, 0);
    cudaStreamWaitEvent(0, evJoin3, 0);

    k_spmm1<<<(n * 16 + 255) / 256, 256>>>(n);
    k_gemm<HID, true><<<(n + 63) / 64, 256>>>(nullptr, W2, b2, mask, n);
    k_spmm2<<<(nidx * 16 + 255) / 256, 256>>>(idx, out, nidx);
}

// round 7
// speedup vs baseline: 1.2336x; 1.1533x over previous
#include <cuda_runtime.h>
#include <cstdint>

#define FEAT 128
#define HID  64
#define NMAX 100000
#define EMAX 1600000

// Scratch (device globals — no runtime allocation allowed)
__device__ float g_h1[NMAX * HID];        // x@W1+b1
__device__ float g_t[NMAX * HID];         // relu(spmm1)*mask  (needed rows only)
__device__ float g_pre[NMAX * HID];       // spmm2 pre-GEMM accum (nidx rows)
__device__ float g_rs[NMAX];              // per-idx-row sum of vals
__device__ int   g_counts[NMAX];          // row degree
__device__ int   g_rowptr[NMAX + 1];      // CSR row pointers
__device__ int   g_cursor[NMAX];          // scatter cursors
__device__ int2  g_csr[EMAX];             // {col, val bits} sorted by row
__device__ int   g_blocksums[256];
__device__ unsigned char g_need[NMAX];    // node needed as spmm1 output row?
__device__ unsigned char g_keep[NMAX];    // node in idx set?

// ---------------------------------------------------------------------------
__global__ void k_init(int n) {
    int tid = blockIdx.x * blockDim.x + threadIdx.x;
    int stride = gridDim.x * blockDim.x;
    for (int t = tid; t < n; t += stride) {
        g_counts[t] = 0;
        g_need[t] = 0;
        g_keep[t] = 0;
    }
}

__global__ void k_keep(const int* __restrict__ idx, int nidx) {
    int i = blockIdx.x * blockDim.x + threadIdx.x;
    if (i < nidx) g_keep[__ldg(idx + i)] = 1;
}

// Fused: degree histogram + need marking, single edge pass.
__global__ void k_count_need(const int* __restrict__ row,
                             const int* __restrict__ col, int E) {
    int e = blockIdx.x * blockDim.x + threadIdx.x;
    if (e >= E) return;
    int r = __ldg(row + e);
    atomicAdd(&g_counts[r], 1);
    if (g_keep[r]) g_need[__ldg(col + e)] = 1;
}

// ---------------------------------------------------------------------------
// Scan stage 1: per-block (1024 elems) exclusive partials + block sums
// ---------------------------------------------------------------------------
__global__ void __launch_bounds__(256) k_scan1(int n) {
    __shared__ int ssum[256];
    int t = threadIdx.x;
    int base = blockIdx.x * 1024 + t * 4;
    int v[4], s = 0;
#pragma unroll
    for (int j = 0; j < 4; j++) {
        int i = base + j;
        v[j] = (i < n) ? g_counts[i] : 0;
        s += v[j];
    }
    ssum[t] = s;
    __syncthreads();
#pragma unroll
    for (int d = 1; d < 256; d <<= 1) {
        int add = (t >= d) ? ssum[t - d] : 0;
        __syncthreads();
        ssum[t] += add;
        __syncthreads();
    }
    int run = ssum[t] - s;
#pragma unroll
    for (int j = 0; j < 4; j++) {
        int i = base + j;
        if (i < n) g_rowptr[i] = run;
        run += v[j];
    }
    if (t == 255) g_blocksums[blockIdx.x] = ssum[255];
}

// ---------------------------------------------------------------------------
// Scan stage 2+3 fused: redundant block-sum scan per block, add offsets,
// init cursors, cap rowptr.
// ---------------------------------------------------------------------------
__global__ void __launch_bounds__(256) k_scan3(int n, int E, int nb) {
    __shared__ int s[256];
    int t = threadIdx.x;
    int bsv = (t < nb) ? g_blocksums[t] : 0;
    s[t] = bsv;
    __syncthreads();
#pragma unroll
    for (int d = 1; d < 256; d <<= 1) {
        int add = (t >= d) ? s[t - d] : 0;
        __syncthreads();
        s[t] += add;
        __syncthreads();
    }
    int i = blockIdx.x * blockDim.x + t;
    if (i < n) {
        int j = i >> 10;
        int off = (j > 0) ? s[j - 1] : 0;
        int v = g_rowptr[i] + off;
        g_rowptr[i] = v;
        g_cursor[i] = v;
    }
    if (i == 0) g_rowptr[n] = E;
}

// ---------------------------------------------------------------------------
// Scatter, 2 edges per thread (MLP=2 on the cursor atomics + csr stores)
// ---------------------------------------------------------------------------
__global__ void k_scatter(const float* __restrict__ vals,
                          const int* __restrict__ row,
                          const int* __restrict__ col, int E) {
    int t = blockIdx.x * blockDim.x + threadIdx.x;
    int e = 2 * t;
    if (e + 1 < E) {
        int2 r2 = *reinterpret_cast<const int2*>(row + e);
        int2 c2 = *reinterpret_cast<const int2*>(col + e);
        float2 v2 = *reinterpret_cast<const float2*>(vals + e);
        int p0 = atomicAdd(&g_cursor[r2.x], 1);
        int p1 = atomicAdd(&g_cursor[r2.y], 1);
        g_csr[p0] = make_int2(c2.x, __float_as_int(v2.x));
        g_csr[p1] = make_int2(c2.y, __float_as_int(v2.y));
    } else if (e < E) {
        int r = __ldg(row + e);
        int pos = atomicAdd(&g_cursor[r], 1);
        g_csr[pos] = make_int2(__ldg(col + e), __float_as_int(__ldg(vals + e)));
    }
}

// ---------------------------------------------------------------------------
// GEMM1 with packed fma.rn.f32x2 (R5-proven). Writes g_h1 via DEVICE-side
// reference (passing a __device__ symbol from host code was the R6 bug).
// ---------------------------------------------------------------------------
#define KCH 32
#define ASTRIDE (KCH + 2)

__device__ __forceinline__ void fma2(unsigned long long& acc,
                                     unsigned long long a,
                                     unsigned long long b) {
    asm("fma.rn.f32x2 %0, %1, %2, %0;" : "+l"(acc) : "l"(a), "l"(b));
}

template <int K>
__global__ void __launch_bounds__(256) k_gemm1(const float* __restrict__ A,
                                               const float* __restrict__ W,
                                               const float* __restrict__ bias,
                                               int nrows) {
    __shared__ float Ws[K * HID];
    __shared__ float As[64 * ASTRIDE];

    float* out = g_h1;   // device-side symbol reference (correct address)

    int tid = threadIdx.x;
    int tx = tid & 7;
    int ty = tid >> 3;
    int row0 = blockIdx.x * 64;

    for (int t = tid; t < K * HID / 4; t += 256)
        reinterpret_cast<float4*>(Ws)[t] =
            reinterpret_cast<const float4*>(W)[t];

    union F2 { unsigned long long u; float2 f; };
    F2 acc[2][4];
#pragma unroll
    for (int i = 0; i < 2; i++)
#pragma unroll
        for (int p = 0; p < 4; p++) acc[i][p].u = 0ull;

    const int vpr = K / 4;

    for (int kc = 0; kc < K; kc += KCH) {
        __syncthreads();
        for (int t = tid; t < 64 * (KCH / 4); t += 256) {
            int r = t >> 3;
            int kv = t & 7;
            float4 a = make_float4(0.f, 0.f, 0.f, 0.f);
            int gr = row0 + r;
            if (gr < nrows)
                a = reinterpret_cast<const float4*>(A)[(size_t)gr * vpr + (kc / 4) + kv];
            float2* p = reinterpret_cast<float2*>(&As[r * ASTRIDE + kv * 4]);
            p[0] = make_float2(a.x, a.y);
            p[1] = make_float2(a.z, a.w);
        }
        __syncthreads();

#pragma unroll 8
        for (int kk = 0; kk < KCH; kk++) {
            int k = kc + kk;
            ulonglong2 wlo = *reinterpret_cast<const ulonglong2*>(&Ws[k * HID + 4 * tx]);
            ulonglong2 whi = *reinterpret_cast<const ulonglong2*>(&Ws[k * HID + 4 * tx + 32]);
#pragma unroll
            for (int i = 0; i < 2; i++) {
                float a = As[(ty * 2 + i) * ASTRIDE + kk];
                unsigned long long aa;
                asm("mov.b64 %0, {%1, %1};" : "=l"(aa) : "f"(a));
                fma2(acc[i][0].u, aa, wlo.x);
                fma2(acc[i][1].u, aa, wlo.y);
                fma2(acc[i][2].u, aa, whi.x);
                fma2(acc[i][3].u, aa, whi.y);
            }
        }
    }

    float4 blo = *reinterpret_cast<const float4*>(bias + 4 * tx);
    float4 bhi = *reinterpret_cast<const float4*>(bias + 4 * tx + 32);
#pragma unroll
    for (int i = 0; i < 2; i++) {
        int r = row0 + ty * 2 + i;
        if (r >= nrows) continue;
        float4 olo, ohi;
        olo.x = acc[i][0].f.x + blo.x;  olo.y = acc[i][0].f.y + blo.y;
        olo.z = acc[i][1].f.x + blo.z;  olo.w = acc[i][1].f.y + blo.w;
        ohi.x = acc[i][2].f.x + bhi.x;  ohi.y = acc[i][2].f.y + bhi.y;
        ohi.z = acc[i][3].f.x + bhi.z;  ohi.w = acc[i][3].f.y + bhi.w;
        *reinterpret_cast<float4*>(&out[(size_t)r * HID + 4 * tx]) = olo;
        *reinterpret_cast<float4*>(&out[(size_t)r * HID + 4 * tx + 32]) = ohi;
    }
}

// ---------------------------------------------------------------------------
// CSR SpMM row body: 16 lanes per row, register accumulation, unroll-2
// ---------------------------------------------------------------------------
__device__ __forceinline__ float4 csr_row_accum(const float* __restrict__ src,
                                                int s, int eEnd, int lane,
                                                float* vsum) {
    float4 acc = make_float4(0.f, 0.f, 0.f, 0.f);
    float vs = 0.f;
    int e = s;
    for (; e + 1 < eEnd; e += 2) {
        int2 cv0 = __ldg(&g_csr[e]);
        int2 cv1 = __ldg(&g_csr[e + 1]);
        float4 x0 = __ldg(reinterpret_cast<const float4*>(src + (size_t)cv0.x * HID) + lane);
        float4 x1 = __ldg(reinterpret_cast<const float4*>(src + (size_t)cv1.x * HID) + lane);
        float v0 = __int_as_float(cv0.y);
        float v1 = __int_as_float(cv1.y);
        vs += v0 + v1;
        acc.x += v0 * x0.x + v1 * x1.x;
        acc.y += v0 * x0.y + v1 * x1.y;
        acc.z += v0 * x0.z + v1 * x1.z;
        acc.w += v0 * x0.w + v1 * x1.w;
    }
    if (e < eEnd) {
        int2 cv = __ldg(&g_csr[e]);
        float4 x = __ldg(reinterpret_cast<const float4*>(src + (size_t)cv.x * HID) + lane);
        float v = __int_as_float(cv.y);
        vs += v;
        acc.x += v * x.x;  acc.y += v * x.y;
        acc.z += v * x.z;  acc.w += v * x.w;
    }
    *vsum = vs;
    return acc;
}

// SpMM1 + fused relu*mask epilogue: t[r] = relu(sum vals*h1[col]) * mask[r]
__global__ void __launch_bounds__(256) k_spmm1(const float* __restrict__ mask,
                                               int n) {
    int g = blockIdx.x * blockDim.x + threadIdx.x;
    int r = g >> 4;
    if (r >= n) return;
    if (!g_need[r]) return;
    int lane = g & 15;
    int s = g_rowptr[r], eEnd = g_rowptr[r + 1];
    float dummy;
    float4 acc = csr_row_accum(g_h1, s, eEnd, lane, &dummy);
    float4 m = __ldg(reinterpret_cast<const float4*>(mask + (size_t)r * HID) + lane);
    acc.x = fmaxf(acc.x, 0.f) * m.x;
    acc.y = fmaxf(acc.y, 0.f) * m.y;
    acc.z = fmaxf(acc.z, 0.f) * m.z;
    acc.w = fmaxf(acc.w, 0.f) * m.w;
    reinterpret_cast<float4*>(g_t + (size_t)r * HID)[lane] = acc;
}

// SpMM2: pre[i] = sum over row idx[i] of vals * t[col];  rs[i] = sum vals
__global__ void __launch_bounds__(256) k_spmm2(const int* __restrict__ idx,
                                               int nidx) {
    int g = blockIdx.x * blockDim.x + threadIdx.x;
    int i = g >> 4;
    if (i >= nidx) return;
    int lane = g & 15;
    int r = __ldg(idx + i);
    int s = g_rowptr[r], eEnd = g_rowptr[r + 1];
    float vs;
    float4 acc = csr_row_accum(g_t, s, eEnd, lane, &vs);
    reinterpret_cast<float4*>(g_pre + (size_t)i * HID)[lane] = acc;
    if (lane == 0) g_rs[i] = vs;
}

// ---------------------------------------------------------------------------
// Mini-GEMM: out[i] = pre[i] @ W2 + rs[i] * b2.  Block = 4 rows x 64 cols.
// ---------------------------------------------------------------------------
__global__ void __launch_bounds__(256) k_gemm3(const float* __restrict__ W2,
                                               const float* __restrict__ b2,
                                               float* __restrict__ out,
                                               int nidx) {
    __shared__ float Ws[HID * HID];   // 16 KB
    __shared__ float As[4 * HID];

    int tid = threadIdx.x;
    int row0 = blockIdx.x * 4;

    for (int t = tid; t < HID * HID / 4; t += 256)
        reinterpret_cast<float4*>(Ws)[t] =
            reinterpret_cast<const float4*>(W2)[t];

    int rr = tid >> 6;    // 0..3
    int kk = tid & 63;
    As[tid] = (row0 + rr < nidx) ? g_pre[(size_t)(row0 + rr) * HID + kk] : 0.f;
    __syncthreads();

    int j = tid & 63;
    float acc = 0.f;
#pragma unroll 16
    for (int k = 0; k < HID; k++)
        acc += As[rr * HID + k] * Ws[k * HID + j];

    int r = row0 + rr;
    if (r < nidx)
        out[(size_t)r * HID + j] = acc + g_rs[r] * __ldg(b2 + j);
}

// ---------------------------------------------------------------------------
extern "C" void kernel_launch(void* const* d_in, const int* in_sizes, int n_in,
                              void* d_out, int out_size) {
    const float* x    = (const float*)d_in[0];
    const float* vals = (const float*)d_in[1];
    const float* W1   = (const float*)d_in[2];
    const float* b1   = (const float*)d_in[3];
    const float* W2   = (const float*)d_in[4];
    const float* b2   = (const float*)d_in[5];
    const float* mask = (const float*)d_in[6];
    const int*   row  = (const int*)d_in[7];
    const int*   col  = (const int*)d_in[8];
    const int*   idx  = (const int*)d_in[9];

    int n    = in_sizes[0] / FEAT;   // 100000
    int E    = in_sizes[1];          // 1600000
    int nidx = in_sizes[9];          // 10000

    float* out = (float*)d_out;
    int nb = (n + 1023) / 1024;      // 98 scan blocks

    // One-time side-stream + events (host resources, not device memory).
    static cudaStream_t s2 = nullptr;
    static cudaEvent_t evFork = nullptr, evJoin2 = nullptr;
    if (s2 == nullptr) {
        cudaStreamCreateWithFlags(&s2, cudaStreamNonBlocking);
        cudaEventCreateWithFlags(&evFork, cudaEventDisableTiming);
        cudaEventCreateWithFlags(&evJoin2, cudaEventDisableTiming);
    }

    // Fork: CSR build + flags on s2, concurrent with GEMM1 on main.
    cudaEventRecord(evFork, 0);
    cudaStreamWaitEvent(s2, evFork, 0);

    k_init<<<256, 256, 0, s2>>>(n);
    k_keep<<<(nidx + 255) / 256, 256, 0, s2>>>(idx, nidx);
    k_count_need<<<(E + 255) / 256, 256, 0, s2>>>(row, col, E);
    k_scan1<<<nb, 256, 0, s2>>>(n);
    k_scan3<<<(n + 255) / 256, 256, 0, s2>>>(n, E, nb);
    k_scatter<<<((E + 1) / 2 + 255) / 256, 256, 0, s2>>>(vals, row, col, E);
    cudaEventRecord(evJoin2, s2);

    // main: GEMM1 concurrent with side-chain
    k_gemm1<FEAT><<<(n + 63) / 64, 256>>>(x, W1, b1, n);

    // Join: spmm1 needs h1 (main) + CSR/need (s2).
    cudaStreamWaitEvent(0, evJoin2, 0);

    k_spmm1<<<(n * 16 + 255) / 256, 256>>>(mask, n);
    k_spmm2<<<(nidx * 16 + 255) / 256, 256>>>(idx, nidx);
    k_gemm3<<<(nidx + 3) / 4, 256>>>(W2, b2, out, nidx);
}

// round 8
// speedup vs baseline: 1.2653x; 1.0257x over previous
#include <cuda_runtime.h>
#include <cuda_fp16.h>
#include <cstdint>

#define FEAT 128
#define HID  64
#define NMAX 100000
#define EMAX 1600000

// Scratch (device globals — no runtime allocation allowed)
__device__ __half g_h1[NMAX * HID];       // x@W1+b1           (fp16 storage)
__device__ __half g_t[NMAX * HID];        // relu(spmm1)*mask  (fp16 storage)
__device__ float  g_pre[NMAX * HID];      // spmm2 pre-GEMM accum (nidx rows)
__device__ float  g_rs[NMAX];             // per-idx-row sum of vals
__device__ int    g_counts[NMAX];         // row degree
__device__ int    g_rowptr[NMAX + 1];     // CSR row pointers
__device__ int    g_cursor[NMAX];         // scatter cursors
__device__ int2   g_csr[EMAX];            // {col, val bits} sorted by row
__device__ int    g_blocksums[256];
__device__ unsigned char g_need[NMAX];    // node needed as spmm1 output row?
__device__ unsigned char g_keep[NMAX];    // node in idx set?

// ---------------------------------------------------------------------------
__global__ void k_init(int n) {
    int tid = blockIdx.x * blockDim.x + threadIdx.x;
    int stride = gridDim.x * blockDim.x;
    for (int t = tid; t < n; t += stride) {
        g_counts[t] = 0;
        g_need[t] = 0;
        g_keep[t] = 0;
    }
}

__global__ void k_keep(const int* __restrict__ idx, int nidx) {
    int i = blockIdx.x * blockDim.x + threadIdx.x;
    if (i < nidx) g_keep[__ldg(idx + i)] = 1;
}

// Fused: degree histogram + need marking, single edge pass.
__global__ void k_count_need(const int* __restrict__ row,
                             const int* __restrict__ col, int E) {
    int e = blockIdx.x * blockDim.x + threadIdx.x;
    if (e >= E) return;
    int r = __ldg(row + e);
    atomicAdd(&g_counts[r], 1);
    if (g_keep[r]) g_need[__ldg(col + e)] = 1;
}

// ---------------------------------------------------------------------------
__global__ void __launch_bounds__(256) k_scan1(int n) {
    __shared__ int ssum[256];
    int t = threadIdx.x;
    int base = blockIdx.x * 1024 + t * 4;
    int v[4], s = 0;
#pragma unroll
    for (int j = 0; j < 4; j++) {
        int i = base + j;
        v[j] = (i < n) ? g_counts[i] : 0;
        s += v[j];
    }
    ssum[t] = s;
    __syncthreads();
#pragma unroll
    for (int d = 1; d < 256; d <<= 1) {
        int add = (t >= d) ? ssum[t - d] : 0;
        __syncthreads();
        ssum[t] += add;
        __syncthreads();
    }
    int run = ssum[t] - s;
#pragma unroll
    for (int j = 0; j < 4; j++) {
        int i = base + j;
        if (i < n) g_rowptr[i] = run;
        run += v[j];
    }
    if (t == 255) g_blocksums[blockIdx.x] = ssum[255];
}

__global__ void __launch_bounds__(256) k_scan3(int n, int E, int nb) {
    __shared__ int s[256];
    int t = threadIdx.x;
    int bsv = (t < nb) ? g_blocksums[t] : 0;
    s[t] = bsv;
    __syncthreads();
#pragma unroll
    for (int d = 1; d < 256; d <<= 1) {
        int add = (t >= d) ? s[t - d] : 0;
        __syncthreads();
        s[t] += add;
        __syncthreads();
    }
    int i = blockIdx.x * blockDim.x + t;
    if (i < n) {
        int j = i >> 10;
        int off = (j > 0) ? s[j - 1] : 0;
        int v = g_rowptr[i] + off;
        g_rowptr[i] = v;
        g_cursor[i] = v;
    }
    if (i == 0) g_rowptr[n] = E;
}

// ---------------------------------------------------------------------------
__global__ void k_scatter(const float* __restrict__ vals,
                          const int* __restrict__ row,
                          const int* __restrict__ col, int E) {
    int t = blockIdx.x * blockDim.x + threadIdx.x;
    int e = 2 * t;
    if (e + 1 < E) {
        int2 r2 = *reinterpret_cast<const int2*>(row + e);
        int2 c2 = *reinterpret_cast<const int2*>(col + e);
        float2 v2 = *reinterpret_cast<const float2*>(vals + e);
        int p0 = atomicAdd(&g_cursor[r2.x], 1);
        int p1 = atomicAdd(&g_cursor[r2.y], 1);
        g_csr[p0] = make_int2(c2.x, __float_as_int(v2.x));
        g_csr[p1] = make_int2(c2.y, __float_as_int(v2.y));
    } else if (e < E) {
        int r = __ldg(row + e);
        int pos = atomicAdd(&g_cursor[r], 1);
        g_csr[pos] = make_int2(__ldg(col + e), __float_as_int(__ldg(vals + e)));
    }
}

// ---------------------------------------------------------------------------
// GEMM1 with packed fma.rn.f32x2 (R5-proven core); epilogue stores fp16.
// ---------------------------------------------------------------------------
#define KCH 32
#define ASTRIDE (KCH + 2)

__device__ __forceinline__ void fma2(unsigned long long& acc,
                                     unsigned long long a,
                                     unsigned long long b) {
    asm("fma.rn.f32x2 %0, %1, %2, %0;" : "+l"(acc) : "l"(a), "l"(b));
}

template <int K>
__global__ void __launch_bounds__(256) k_gemm1(const float* __restrict__ A,
                                               const float* __restrict__ W,
                                               const float* __restrict__ bias,
                                               int nrows) {
    __shared__ float Ws[K * HID];
    __shared__ float As[64 * ASTRIDE];

    __half* out = g_h1;

    int tid = threadIdx.x;
    int tx = tid & 7;
    int ty = tid >> 3;
    int row0 = blockIdx.x * 64;

    for (int t = tid; t < K * HID / 4; t += 256)
        reinterpret_cast<float4*>(Ws)[t] =
            reinterpret_cast<const float4*>(W)[t];

    union F2 { unsigned long long u; float2 f; };
    F2 acc[2][4];
#pragma unroll
    for (int i = 0; i < 2; i++)
#pragma unroll
        for (int p = 0; p < 4; p++) acc[i][p].u = 0ull;

    const int vpr = K / 4;

    for (int kc = 0; kc < K; kc += KCH) {
        __syncthreads();
        for (int t = tid; t < 64 * (KCH / 4); t += 256) {
            int r = t >> 3;
            int kv = t & 7;
            float4 a = make_float4(0.f, 0.f, 0.f, 0.f);
            int gr = row0 + r;
            if (gr < nrows)
                a = reinterpret_cast<const float4*>(A)[(size_t)gr * vpr + (kc / 4) + kv];
            float2* p = reinterpret_cast<float2*>(&As[r * ASTRIDE + kv * 4]);
            p[0] = make_float2(a.x, a.y);
            p[1] = make_float2(a.z, a.w);
        }
        __syncthreads();

#pragma unroll 8
        for (int kk = 0; kk < KCH; kk++) {
            int k = kc + kk;
            ulonglong2 wlo = *reinterpret_cast<const ulonglong2*>(&Ws[k * HID + 4 * tx]);
            ulonglong2 whi = *reinterpret_cast<const ulonglong2*>(&Ws[k * HID + 4 * tx + 32]);
#pragma unroll
            for (int i = 0; i < 2; i++) {
                float a = As[(ty * 2 + i) * ASTRIDE + kk];
                unsigned long long aa;
                asm("mov.b64 %0, {%1, %1};" : "=l"(aa) : "f"(a));
                fma2(acc[i][0].u, aa, wlo.x);
                fma2(acc[i][1].u, aa, wlo.y);
                fma2(acc[i][2].u, aa, whi.x);
                fma2(acc[i][3].u, aa, whi.y);
            }
        }
    }

    float4 blo = *reinterpret_cast<const float4*>(bias + 4 * tx);
    float4 bhi = *reinterpret_cast<const float4*>(bias + 4 * tx + 32);
#pragma unroll
    for (int i = 0; i < 2; i++) {
        int r = row0 + ty * 2 + i;
        if (r >= nrows) continue;
        union { __half2 h[2]; uint2 u; } plo, phi;
        plo.h[0] = __floats2half2_rn(acc[i][0].f.x + blo.x, acc[i][0].f.y + blo.y);
        plo.h[1] = __floats2half2_rn(acc[i][1].f.x + blo.z, acc[i][1].f.y + blo.w);
        phi.h[0] = __floats2half2_rn(acc[i][2].f.x + bhi.x, acc[i][2].f.y + bhi.y);
        phi.h[1] = __floats2half2_rn(acc[i][3].f.x + bhi.z, acc[i][3].f.y + bhi.w);
        *reinterpret_cast<uint2*>(&out[(size_t)r * HID + 4 * tx]) = plo.u;
        *reinterpret_cast<uint2*>(&out[(size_t)r * HID + 4 * tx + 32]) = phi.u;
    }
}

// ---------------------------------------------------------------------------
// CSR SpMM row body on fp16 source: 8 lanes per row, each lane owns 8 cols
// (one uint4 = 8 halves per gather). fp32 accumulation, unroll-2 (MLP=2).
// ---------------------------------------------------------------------------
union HU { uint4 u; __half2 h[4]; };

__device__ __forceinline__ void csr_row_accum_h(const __half* __restrict__ src,
                                                int s, int eEnd, int lane,
                                                float acc[8], float* vsum) {
#pragma unroll
    for (int p = 0; p < 8; p++) acc[p] = 0.f;
    float vs = 0.f;
    int e = s;
    for (; e + 1 < eEnd; e += 2) {
        int2 cv0 = __ldg(&g_csr[e]);
        int2 cv1 = __ldg(&g_csr[e + 1]);
        HU q0, q1;
        q0.u = *reinterpret_cast<const uint4*>(src + (size_t)cv0.x * HID + lane * 8);
        q1.u = *reinterpret_cast<const uint4*>(src + (size_t)cv1.x * HID + lane * 8);
        float v0 = __int_as_float(cv0.y);
        float v1 = __int_as_float(cv1.y);
        vs += v0 + v1;
#pragma unroll
        for (int p = 0; p < 4; p++) {
            float2 f0 = __half22float2(q0.h[p]);
            float2 f1 = __half22float2(q1.h[p]);
            acc[2 * p]     += v0 * f0.x + v1 * f1.x;
            acc[2 * p + 1] += v0 * f0.y + v1 * f1.y;
        }
    }
    if (e < eEnd) {
        int2 cv = __ldg(&g_csr[e]);
        HU q;
        q.u = *reinterpret_cast<const uint4*>(src + (size_t)cv.x * HID + lane * 8);
        float v = __int_as_float(cv.y);
        vs += v;
#pragma unroll
        for (int p = 0; p < 4; p++) {
            float2 f = __half22float2(q.h[p]);
            acc[2 * p]     += v * f.x;
            acc[2 * p + 1] += v * f.y;
        }
    }
    *vsum = vs;
}

// SpMM1 + fused relu*mask epilogue -> t (fp16)
__global__ void __launch_bounds__(256) k_spmm1(const float* __restrict__ mask,
                                               int n) {
    int g = blockIdx.x * blockDim.x + threadIdx.x;
    int r = g >> 3;
    if (r >= n) return;
    if (!g_need[r]) return;
    int lane = g & 7;
    int s = g_rowptr[r], eEnd = g_rowptr[r + 1];
    float acc[8], dummy;
    csr_row_accum_h(g_h1, s, eEnd, lane, acc, &dummy);
    float4 m0 = __ldg(reinterpret_cast<const float4*>(mask + (size_t)r * HID + lane * 8));
    float4 m1 = __ldg(reinterpret_cast<const float4*>(mask + (size_t)r * HID + lane * 8 + 4));
    union { __half2 h[4]; uint4 u; } o;
    o.h[0] = __floats2half2_rn(fmaxf(acc[0], 0.f) * m0.x, fmaxf(acc[1], 0.f) * m0.y);
    o.h[1] = __floats2half2_rn(fmaxf(acc[2], 0.f) * m0.z, fmaxf(acc[3], 0.f) * m0.w);
    o.h[2] = __floats2half2_rn(fmaxf(acc[4], 0.f) * m1.x, fmaxf(acc[5], 0.f) * m1.y);
    o.h[3] = __floats2half2_rn(fmaxf(acc[6], 0.f) * m1.z, fmaxf(acc[7], 0.f) * m1.w);
    *reinterpret_cast<uint4*>(g_t + (size_t)r * HID + lane * 8) = o.u;
}

// SpMM2: pre[i] = sum over row idx[i] of vals * t[col];  rs[i] = sum vals
__global__ void __launch_bounds__(256) k_spmm2(const int* __restrict__ idx,
                                               int nidx) {
    int g = blockIdx.x * blockDim.x + threadIdx.x;
    int i = g >> 3;
    if (i >= nidx) return;
    int lane = g & 7;
    int r = __ldg(idx + i);
    int s = g_rowptr[r], eEnd = g_rowptr[r + 1];
    float acc[8], vs;
    csr_row_accum_h(g_t, s, eEnd, lane, acc, &vs);
    float* dst = g_pre + (size_t)i * HID + lane * 8;
    *reinterpret_cast<float4*>(dst)     = make_float4(acc[0], acc[1], acc[2], acc[3]);
    *reinterpret_cast<float4*>(dst + 4) = make_float4(acc[4], acc[5], acc[6], acc[7]);
    if (lane == 0) g_rs[i] = vs;
}

// ---------------------------------------------------------------------------
// Mini-GEMM: out[i] = pre[i] @ W2 + rs[i] * b2.  Block = 4 rows x 64 cols.
// ---------------------------------------------------------------------------
__global__ void __launch_bounds__(256) k_gemm3(const float* __restrict__ W2,
                                               const float* __restrict__ b2,
                                               float* __restrict__ out,
                                               int nidx) {
    __shared__ float Ws[HID * HID];   // 16 KB
    __shared__ float As[4 * HID];

    int tid = threadIdx.x;
    int row0 = blockIdx.x * 4;

    for (int t = tid; t < HID * HID / 4; t += 256)
        reinterpret_cast<float4*>(Ws)[t] =
            reinterpret_cast<const float4*>(W2)[t];

    int rr = tid >> 6;    // 0..3
    int kk = tid & 63;
    As[tid] = (row0 + rr < nidx) ? g_pre[(size_t)(row0 + rr) * HID + kk] : 0.f;
    __syncthreads();

    int j = tid & 63;
    float acc = 0.f;
#pragma unroll 16
    for (int k = 0; k < HID; k++)
        acc += As[rr * HID + k] * Ws[k * HID + j];

    int r = row0 + rr;
    if (r < nidx)
        out[(size_t)r * HID + j] = acc + g_rs[r] * __ldg(b2 + j);
}

// ---------------------------------------------------------------------------
extern "C" void kernel_launch(void* const* d_in, const int* in_sizes, int n_in,
                              void* d_out, int out_size) {
    const float* x    = (const float*)d_in[0];
    const float* vals = (const float*)d_in[1];
    const float* W1   = (const float*)d_in[2];
    const float* b1   = (const float*)d_in[3];
    const float* W2   = (const float*)d_in[4];
    const float* b2   = (const float*)d_in[5];
    const float* mask = (const float*)d_in[6];
    const int*   row  = (const int*)d_in[7];
    const int*   col  = (const int*)d_in[8];
    const int*   idx  = (const int*)d_in[9];

    int n    = in_sizes[0] / FEAT;   // 100000
    int E    = in_sizes[1];          // 1600000
    int nidx = in_sizes[9];          // 10000

    float* out = (float*)d_out;
    int nb = (n + 1023) / 1024;      // 98 scan blocks

    // One-time side-stream + events (host resources, not device memory).
    static cudaStream_t s2 = nullptr;
    static cudaEvent_t evFork = nullptr, evJoin2 = nullptr;
    if (s2 == nullptr) {
        cudaStreamCreateWithFlags(&s2, cudaStreamNonBlocking);
        cudaEventCreateWithFlags(&evFork, cudaEventDisableTiming);
        cudaEventCreateWithFlags(&evJoin2, cudaEventDisableTiming);
    }

    // Fork: CSR build + flags on s2, concurrent with GEMM1 on main.
    cudaEventRecord(evFork, 0);
    cudaStreamWaitEvent(s2, evFork, 0);

    k_init<<<256, 256, 0, s2>>>(n);
    k_keep<<<(nidx + 255) / 256, 256, 0, s2>>>(idx, nidx);
    k_count_need<<<(E + 255) / 256, 256, 0, s2>>>(row, col, E);
    k_scan1<<<nb, 256, 0, s2>>>(n);
    k_scan3<<<(n + 255) / 256, 256, 0, s2>>>(n, E, nb);
    k_scatter<<<((E + 1) / 2 + 255) / 256, 256, 0, s2>>>(vals, row, col, E);
    cudaEventRecord(evJoin2, s2);

    // main: GEMM1 concurrent with side-chain
    k_gemm1<FEAT><<<(n + 63) / 64, 256>>>(x, W1, b1, n);

    // Join: spmm1 needs h1 (main) + CSR/need (s2).
    cudaStreamWaitEvent(0, evJoin2, 0);

    k_spmm1<<<(n * 8 + 255) / 256, 256>>>(mask, n);
    k_spmm2<<<(nidx * 8 + 255) / 256, 256>>>(idx, nidx);
    k_gemm3<<<(nidx + 3) / 4, 256>>>(W2, b2, out, nidx);
}